// round 10
// baseline (speedup 1.0000x reference)
#include <cuda_runtime.h>
#include <cuda_bf16.h>
#include <math.h>

#define BB 2
#define CC 256
#define HWN 4096
#define KCN 32
#define RDN 16
#define NO 384
#define EPSV 1e-5f

typedef unsigned long long u64;
typedef unsigned int u32;
typedef __nv_bfloat16 bf16;

// ---------------- scratch ----------------
__device__ float g_mean[BB*CC];
__device__ float g_gate[BB*CC];
__device__ bf16  g_xb  [BB*HWN*CC];     // [b][m][c]
__device__ bf16  g_Wb  [BB*NO*CC];      // [b][o][c]  (gate folded into K rows)
__device__ bf16  g_Wob [CC*CC];         // [o][c]
__device__ bf16  g_Qb  [BB*HWN*KCN];    // [b][m][k]
__device__ bf16  g_Kb  [BB*HWN*KCN];
__device__ float g_b1r [BB*HWN*KCN];    // [b][m][k] fp32 pre-smooth (relu'd)
__device__ float g_b2r [BB*HWN*KCN];
__device__ bf16  g_b1b [BB*HWN*KCN];    // smoothed
__device__ bf16  g_b2b [BB*HWN*KCN];
__device__ bf16  g_Vb  [BB*CC*HWN];     // [b][c][m]
__device__ bf16  g_ctxb[BB*HWN*CC];     // [b][n][c]

__device__ __forceinline__ float sigm(float x){
    return __fdividef(1.0f, 1.0f + __expf(-x));
}
__device__ __forceinline__ void cpa16(u32 dst, const void* src){
    asm volatile("cp.async.ca.shared.global [%0], [%1], 16;" :: "r"(dst), "l"(src));
}
__device__ __forceinline__ void cpa_commit(){ asm volatile("cp.async.commit_group;"); }
__device__ __forceinline__ u32 bf2(float lo, float hi){
    u32 r; asm("cvt.rn.bf16x2.f32 %0, %1, %2;" : "=r"(r) : "f"(hi), "f"(lo)); return r;
}
__device__ __forceinline__ void mma16816(float* c, const u32* a, u32 b0, u32 b1){
    asm("mma.sync.aligned.m16n8k16.row.col.f32.bf16.bf16.f32 "
        "{%0,%1,%2,%3}, {%4,%5,%6,%7}, {%8,%9}, {%0,%1,%2,%3};"
        : "+f"(c[0]),"+f"(c[1]),"+f"(c[2]),"+f"(c[3])
        : "r"(a[0]),"r"(a[1]),"r"(a[2]),"r"(a[3]), "r"(b0),"r"(b1));
}

// ---------------- 1) per-(b,c) spatial mean ----------------
__global__ void k_mean(const float* __restrict__ x){
    int b = blockIdx.y;
    int c = blockIdx.x*8 + (threadIdx.x>>5);
    int lane = threadIdx.x & 31;
    const float* p = x + ((size_t)(b*CC + c))*HWN;
    float s = 0.f;
    for(int i=lane;i<HWN;i+=32) s += p[i];
    #pragma unroll
    for(int o=16;o;o>>=1) s += __shfl_xor_sync(0xffffffffu, s, o);
    if(lane==0) g_mean[b*CC+c] = s * (1.0f/HWN);
}

// ---------------- 2) GatherExcite MLP -> sigmoid gate ----------------
__global__ void k_gate(const float* __restrict__ w1, const float* __restrict__ b1,
                       const float* __restrict__ w2, const float* __restrict__ b2){
    __shared__ float sm[CC];
    __shared__ float sg[RDN];
    int b = blockIdx.x, t = threadIdx.x;
    sm[t] = g_mean[b*CC + t];
    __syncthreads();
    if(t < RDN){
        float a = b1[t];
        for(int c=0;c<CC;c++) a += w1[t*CC + c]*sm[c];
        sg[t] = fmaxf(a, 0.f);
    }
    __syncthreads();
    float a = b2[t];
    #pragma unroll
    for(int r=0;r<RDN;r++) a += w2[t*RDN + r]*sg[r];
    g_gate[b*CC + t] = sigm(a);
}

// ---------------- 2b) x transpose+convert: [b][c][m] f32 -> [b][m][c] bf16 -------
__global__ void __launch_bounds__(128) k_xpose(const float* __restrict__ x){
    __shared__ float sm[32][129];
    int b = blockIdx.z, c0 = blockIdx.y*32, m0 = blockIdx.x*128;
    int t = threadIdx.x;
    #pragma unroll 4
    for(int ci=0; ci<32; ci++)
        sm[ci][t] = x[((size_t)(b*CC + c0 + ci))*HWN + m0 + t];
    __syncthreads();
    u32 pk[16];
    #pragma unroll
    for(int i=0;i<16;i++) pk[i] = bf2(sm[2*i][t], sm[2*i+1][t]);
    uint4* dst = (uint4*)(g_xb + ((size_t)(b*HWN) + m0 + t)*CC + c0);
    #pragma unroll
    for(int q=0;q<4;q++) dst[q] = ((uint4*)pk)[q];
}

// ---------------- 2c) weight prep: bf16 [o][c], gate folded ----------------
__global__ void k_wprep(const float* __restrict__ Wq, const float* __restrict__ Wk,
                        const float* __restrict__ Wb1, const float* __restrict__ Wb2,
                        const float* __restrict__ Wv, const float* __restrict__ Wo){
    int idx = blockIdx.x*256 + threadIdx.x;
    if(idx < BB*NO*CC){
        int c = idx & 255;
        int o = (idx >> 8) % NO;
        int b = idx / (NO*CC);
        float w;
        if(o < 32)       w = Wq [o*CC + c];
        else if(o < 64)  w = Wk [(o-32)*CC + c] * g_gate[b*CC + c];
        else if(o < 96)  w = Wb1[(o-64)*CC + c];
        else if(o < 128) w = Wb2[(o-96)*CC + c];
        else             w = Wv [(o-128)*CC + c];
        g_Wb[idx] = __float2bfloat16(w);
    } else {
        int j = idx - BB*NO*CC;   // CC*CC elems
        g_Wob[j] = __float2bfloat16(Wo[j]);
    }
}

// ---------------- 3) fused projections on HMMA (256 thr, 8 warps, 16 rows/warp) --
// smem: A 2x[128][72] bf16 (18432 ea) | B 2x[64][72] bf16 (9216 ea)
#define PJ_A_SZ  18432
#define PJ_B_OFF 36864
#define PJ_B_SZ  9216
#define PJ_SMEM  55296

__global__ void __launch_bounds__(256,1) k_projmm(){
    extern __shared__ char smr[];
    const u32 sb = (u32)__cvta_generic_to_shared(smr);
    const int t    = threadIdx.x;
    const int w    = t >> 5;
    const int lane = t & 31;
    const int g    = lane >> 2;
    const int tig  = lane & 3;
    const int b    = blockIdx.z;
    const int yblk = blockIdx.y;         // 0:{Q,K} 1:{b1,b2} 2..5:V
    const int m0   = blockIdx.x*128;
    const int o0   = yblk*64;

    const bf16* asrc = g_xb + ((size_t)(b*HWN) + m0)*CC;
    const bf16* bsrc = g_Wb + ((size_t)(b*NO)  + o0)*CC;

    float acc[8][4];
    #pragma unroll
    for(int bn=0;bn<8;bn++)
        #pragma unroll
        for(int q=0;q<4;q++) acc[bn][q]=0.f;

    {
        #pragma unroll
        for(int u=0;u<4;u++){
            int ch = t + u*256;             // 1024: 128 rows x 8
            int row = ch>>3, j = ch&7;
            cpa16(sb + (u32)(row*144 + j*16), asrc + (size_t)row*CC + j*8);
        }
        #pragma unroll
        for(int u=0;u<2;u++){
            int ch = t + u*256;             // 512: 64 rows x 8
            int row = ch>>3, j = ch&7;
            cpa16(sb + PJ_B_OFF + (u32)(row*144 + j*16), bsrc + (size_t)row*CC + j*8);
        }
        cpa_commit();
    }

    for(int cc=0; cc<4; cc++){
        const int cur = cc & 1;
        __syncthreads();
        if(cc+1 < 4){
            const int nb = 1-cur;
            #pragma unroll
            for(int u=0;u<4;u++){
                int ch = t + u*256;
                int row = ch>>3, j = ch&7;
                cpa16(sb + (u32)(nb*PJ_A_SZ + row*144 + j*16),
                      asrc + (size_t)row*CC + (cc+1)*64 + j*8);
            }
            #pragma unroll
            for(int u=0;u<2;u++){
                int ch = t + u*256;
                int row = ch>>3, j = ch&7;
                cpa16(sb + (u32)(PJ_B_OFF + nb*PJ_B_SZ + row*144 + j*16),
                      bsrc + (size_t)row*CC + (cc+1)*64 + j*8);
            }
            cpa_commit();
            asm volatile("cp.async.wait_group 1;" ::: "memory");
        } else {
            asm volatile("cp.async.wait_group 0;" ::: "memory");
        }
        __syncthreads();

        const bf16* As = (const bf16*)(smr + cur*PJ_A_SZ);
        const bf16* Bs = (const bf16*)(smr + PJ_B_OFF + cur*PJ_B_SZ);
        #pragma unroll
        for(int ks=0;ks<4;ks++){
            u32 af[4];
            const bf16* ar = As + (w*16 + g)*72 + ks*16 + 2*tig;
            af[0] = *(const u32*)ar;
            af[1] = *(const u32*)(ar + 8*72);
            af[2] = *(const u32*)(ar + 8);
            af[3] = *(const u32*)(ar + 8*72 + 8);
            #pragma unroll
            for(int bn=0;bn<8;bn++){
                const bf16* br = Bs + (bn*8 + g)*72 + ks*16 + 2*tig;
                u32 b0 = *(const u32*)br, b1 = *(const u32*)(br + 8);
                mma16816(acc[bn], af, b0, b1);
            }
        }
    }

    if(yblk == 0){
        int r0g = m0 + w*16 + g;
        #pragma unroll
        for(int bn=0;bn<8;bn++){
            int o = bn*8 + 2*tig;
            bf16* base = (o<32) ? g_Qb : g_Kb;
            int oo = o & 31;
            *(u32*)(base + ((size_t)(b*HWN) + r0g    )*KCN + oo) = bf2(acc[bn][0], acc[bn][1]);
            *(u32*)(base + ((size_t)(b*HWN) + r0g + 8)*KCN + oo) = bf2(acc[bn][2], acc[bn][3]);
        }
    } else if(yblk == 1){
        int r0g = m0 + w*16 + g;
        #pragma unroll
        for(int bn=0;bn<8;bn++){
            int o = bn*8 + 2*tig;
            float* base = (o<32) ? g_b1r : g_b2r;
            int oo = o & 31;
            float2 v0; v0.x = fmaxf(acc[bn][0],0.f); v0.y = fmaxf(acc[bn][1],0.f);
            float2 v1; v1.x = fmaxf(acc[bn][2],0.f); v1.y = fmaxf(acc[bn][3],0.f);
            *(float2*)(base + ((size_t)(b*HWN) + r0g    )*KCN + oo) = v0;
            *(float2*)(base + ((size_t)(b*HWN) + r0g + 8)*KCN + oo) = v1;
        }
    } else {
        // V: transpose epilogue -> g_Vb[b][c][m] bf16
        __syncthreads();
        float* smf = (float*)smr;         // [64 cols][132]
        int rl = w*16 + g;
        #pragma unroll
        for(int bn=0;bn<8;bn++){
            int col = bn*8 + 2*tig;
            smf[col*132 + rl]         = acc[bn][0];
            smf[(col+1)*132 + rl]     = acc[bn][1];
            smf[col*132 + rl + 8]     = acc[bn][2];
            smf[(col+1)*132 + rl + 8] = acc[bn][3];
        }
        __syncthreads();
        int cc = t >> 2, q4 = t & 3;
        int c = (yblk-2)*64 + cc;
        bf16* dst = g_Vb + ((size_t)(b*CC) + c)*HWN + m0 + q4*32;
        u32 pk[16];
        #pragma unroll
        for(int j=0;j<16;j++)
            pk[j] = bf2(smf[cc*132 + q4*32 + 2*j], smf[cc*132 + q4*32 + 2*j + 1]);
        #pragma unroll
        for(int q=0;q<4;q++) ((uint4*)dst)[q] = ((uint4*)pk)[q];
    }
}

// ---------------- 5) 3-tap box smoothing ([m][k] layout) ----------------
__global__ void k_smooth(){
    int idx = blockIdx.x*256 + threadIdx.x;
    int k = idx & 31;
    int m = (idx >> 5) & (HWN-1);
    int b = idx >> 17;
    size_t base = ((size_t)(b*HWN) + m)*KCN + k;
    float a1 = g_b1r[base], a2 = g_b2r[base];
    if(m > 0)      { a1 += g_b1r[base-KCN]; a2 += g_b2r[base-KCN]; }
    if(m < HWN-1)  { a1 += g_b1r[base+KCN]; a2 += g_b2r[base+KCN]; }
    g_b1b[base] = __float2bfloat16(a1);
    g_b2b[base] = __float2bfloat16(a2);
}

// ---------------- 6) fused attention: HMMA, 8 warps (2/SMSP), key-split pairs ---
// smem: V 2x[256][72 bf16] | K 2x[64][40 bf16] | B2 2x[64][40 bf16]
#define VT_SZ    36864
#define KT_OFF   73728
#define KT_SZ    5120
#define B2_OFF   83968
#define B2_SZ    5120
#define ATTN_SMEM 94208

__device__ __forceinline__ void attn_prefetch(u32 sb, int t, int b, int key0, int buf){
    #pragma unroll
    for(int u=0;u<8;u++){
        int ch = t + u*256;                 // 2048: 256 rows x 8
        int row = ch>>3, j = ch&7;
        cpa16(sb + (u32)(buf*VT_SZ + row*144 + j*16),
              g_Vb + ((size_t)b*CC + row)*HWN + key0 + j*8);
    }
    {
        int key = t>>2, j = t&3;            // 256: 64 rows x 4
        cpa16(sb + (u32)(KT_OFF + buf*KT_SZ + key*80 + j*16),
              g_Kb + ((size_t)(b*HWN) + key0 + key)*KCN + j*8);
        cpa16(sb + (u32)(B2_OFF + buf*B2_SZ + key*80 + j*16),
              g_b2b + ((size_t)(b*HWN) + key0 + key)*KCN + j*8);
    }
}

__global__ void __launch_bounds__(256,1) k_attn(const float* __restrict__ wgb){
    extern __shared__ char smr[];
    const u32 sb = (u32)__cvta_generic_to_shared(smr);
    const int t    = threadIdx.x;
    const int w    = t >> 5;
    const int wm   = w & 3;        // row-block warp
    const int kh   = w >> 2;       // key half (0: keys 0-31, 1: keys 32-63 of tile)
    const int lane = t & 31;
    const int g    = lane >> 2;
    const int tig  = lane & 3;
    const int b    = blockIdx.y;
    const int row0 = blockIdx.x*64 + wm*16;

    attn_prefetch(sb, t, b, 0, 0);
    cpa_commit();

    u32 qf[2][4], b1f[2][4];
    {
        const bf16* q0 = g_Qb  + ((size_t)(b*HWN) + row0 + g)*KCN;
        const bf16* c0 = g_b1b + ((size_t)(b*HWN) + row0 + g)*KCN;
        #pragma unroll
        for(int ks=0;ks<2;ks++){
            qf[ks][0]  = *(const u32*)(q0 + ks*16 + 2*tig);
            qf[ks][1]  = *(const u32*)(q0 + 8*KCN + ks*16 + 2*tig);
            qf[ks][2]  = *(const u32*)(q0 + ks*16 + 2*tig + 8);
            qf[ks][3]  = *(const u32*)(q0 + 8*KCN + ks*16 + 2*tig + 8);
            b1f[ks][0] = *(const u32*)(c0 + ks*16 + 2*tig);
            b1f[ks][1] = *(const u32*)(c0 + 8*KCN + ks*16 + 2*tig);
            b1f[ks][2] = *(const u32*)(c0 + ks*16 + 2*tig + 8);
            b1f[ks][3] = *(const u32*)(c0 + 8*KCN + ks*16 + 2*tig + 8);
        }
    }

    float pv[32][4];
    #pragma unroll
    for(int i=0;i<32;i++){ pv[i][0]=0.f; pv[i][1]=0.f; pv[i][2]=0.f; pv[i][3]=0.f; }
    float ls0 = 0.f, ls1 = 0.f;
    const float cgb = wgb[0] * (1.0f/9.0f);

    for(int tile=0; tile<HWN/64; tile++){
        const int cur = tile & 1;
        __syncthreads();
        if(tile+1 < HWN/64){
            attn_prefetch(sb, t, b, (tile+1)*64, 1-cur);
            cpa_commit();
            asm volatile("cp.async.wait_group 1;" ::: "memory");
        } else {
            asm volatile("cp.async.wait_group 0;" ::: "memory");
        }
        __syncthreads();

        const bf16* Ks  = (const bf16*)(smr + KT_OFF + cur*KT_SZ);
        const bf16* B2s = (const bf16*)(smr + B2_OFF + cur*B2_SZ);
        const bf16* Vs  = (const bf16*)(smr + cur*VT_SZ);

        u32 pa[4][2];
        #pragma unroll
        for(int nt=0; nt<4; nt++){
            int gnt = kh*4 + nt;
            float sa[4] = {0.f,0.f,0.f,0.f};
            float pl[4] = {0.f,0.f,0.f,0.f};
            const bf16* kr = Ks  + (gnt*8 + g)*40;
            const bf16* br = B2s + (gnt*8 + g)*40;
            #pragma unroll
            for(int ks=0;ks<2;ks++){
                u32 k0  = *(const u32*)(kr + ks*16 + 2*tig);
                u32 k1  = *(const u32*)(kr + ks*16 + 2*tig + 8);
                u32 bb0 = *(const u32*)(br + ks*16 + 2*tig);
                u32 bb1 = *(const u32*)(br + ks*16 + 2*tig + 8);
                mma16816(sa, qf[ks],  k0,  k1);
                mma16816(pl, b1f[ks], bb0, bb1);
            }
            float e0 = __expf(sa[0] * sigm(cgb*pl[0]));
            float e1 = __expf(sa[1] * sigm(cgb*pl[1]));
            float e2 = __expf(sa[2] * sigm(cgb*pl[2]));
            float e3 = __expf(sa[3] * sigm(cgb*pl[3]));
            ls0 += e0 + e1;
            ls1 += e2 + e3;
            pa[nt][0] = bf2(e0, e1);
            pa[nt][1] = bf2(e2, e3);
        }

        #pragma unroll
        for(int cnt=0; cnt<32; cnt++){
            const bf16* vr = Vs + (cnt*8 + g)*72 + kh*32;
            #pragma unroll
            for(int ks=0;ks<2;ks++){
                u32 v0 = *(const u32*)(vr + 16*ks + 2*tig);
                u32 v1 = *(const u32*)(vr + 16*ks + 2*tig + 8);
                u32 af[4] = { pa[2*ks][0], pa[2*ks][1], pa[2*ks+1][0], pa[2*ks+1][1] };
                mma16816(pv[cnt], af, v0, v1);
            }
        }
    }

    #pragma unroll
    for(int o=1;o<4;o<<=1){
        ls0 += __shfl_xor_sync(0xffffffffu, ls0, o);
        ls1 += __shfl_xor_sync(0xffffffffu, ls1, o);
    }

    __syncthreads();
    float* smf = (float*)smr;       // [4*32][131]
    if(kh == 1){
        float* dst = smf + (size_t)(wm*32 + lane)*131;
        #pragma unroll
        for(int cnt=0;cnt<32;cnt++){
            dst[cnt*4+0] = pv[cnt][0]; dst[cnt*4+1] = pv[cnt][1];
            dst[cnt*4+2] = pv[cnt][2]; dst[cnt*4+3] = pv[cnt][3];
        }
        dst[128] = ls0; dst[129] = ls1;
    }
    __syncthreads();
    if(kh == 0){
        const float* src = smf + (size_t)(wm*32 + lane)*131;
        #pragma unroll
        for(int cnt=0;cnt<32;cnt++){
            pv[cnt][0] += src[cnt*4+0]; pv[cnt][1] += src[cnt*4+1];
            pv[cnt][2] += src[cnt*4+2]; pv[cnt][3] += src[cnt*4+3];
        }
        ls0 += src[128]; ls1 += src[129];

        float rl0 = __fdividef(1.0f, ls0);
        float rl1 = __fdividef(1.0f, ls1);
        u32* d0 = (u32*)(g_ctxb + ((size_t)(b*HWN) + row0 + g    )*CC);
        u32* d8 = (u32*)(g_ctxb + ((size_t)(b*HWN) + row0 + g + 8)*CC);
        #pragma unroll
        for(int cnt=0; cnt<32; cnt++){
            d0[cnt*4 + tig] = bf2(pv[cnt][0]*rl0, pv[cnt][1]*rl0);
            d8[cnt*4 + tig] = bf2(pv[cnt][2]*rl1, pv[cnt][3]*rl1);
        }
    }
}

// ---------------- 7) output projection (HMMA, 256 thr) + BN + ReLU + residual ---
__global__ void __launch_bounds__(256,1) k_final(
    const float* __restrict__ x,
    const float* __restrict__ bn_scale, const float* __restrict__ bn_bias,
    const float* __restrict__ bn_mean, const float* __restrict__ bn_var,
    const float* __restrict__ gamma, float* __restrict__ out)
{
    extern __shared__ char smr[];
    const u32 sb = (u32)__cvta_generic_to_shared(smr);
    const int t    = threadIdx.x;
    const int w    = t >> 5;
    const int lane = t & 31;
    const int g    = lane >> 2;
    const int tig  = lane & 3;
    const int b    = blockIdx.z;
    const int c0   = blockIdx.y*64;
    const int m0   = blockIdx.x*128;

    const bf16* asrc = g_ctxb + ((size_t)(b*HWN) + m0)*CC;
    const bf16* bsrc = g_Wob + (size_t)c0*CC;

    float acc[8][4];
    #pragma unroll
    for(int bn=0;bn<8;bn++)
        #pragma unroll
        for(int q=0;q<4;q++) acc[bn][q]=0.f;

    {
        #pragma unroll
        for(int u=0;u<4;u++){
            int ch = t + u*256;
            int row = ch>>3, j = ch&7;
            cpa16(sb + (u32)(row*144 + j*16), asrc + (size_t)row*CC + j*8);
        }
        #pragma unroll
        for(int u=0;u<2;u++){
            int ch = t + u*256;
            int row = ch>>3, j = ch&7;
            cpa16(sb + PJ_B_OFF + (u32)(row*144 + j*16), bsrc + (size_t)row*CC + j*8);
        }
        cpa_commit();
    }

    for(int cc=0; cc<4; cc++){
        const int cur = cc & 1;
        __syncthreads();
        if(cc+1 < 4){
            const int nb = 1-cur;
            #pragma unroll
            for(int u=0;u<4;u++){
                int ch = t + u*256;
                int row = ch>>3, j = ch&7;
                cpa16(sb + (u32)(nb*PJ_A_SZ + row*144 + j*16),
                      asrc + (size_t)row*CC + (cc+1)*64 + j*8);
            }
            #pragma unroll
            for(int u=0;u<2;u++){
                int ch = t + u*256;
                int row = ch>>3, j = ch&7;
                cpa16(sb + (u32)(PJ_B_OFF + nb*PJ_B_SZ + row*144 + j*16),
                      bsrc + (size_t)row*CC + (cc+1)*64 + j*8);
            }
            cpa_commit();
            asm volatile("cp.async.wait_group 1;" ::: "memory");
        } else {
            asm volatile("cp.async.wait_group 0;" ::: "memory");
        }
        __syncthreads();

        const bf16* As = (const bf16*)(smr + cur*PJ_A_SZ);
        const bf16* Bs = (const bf16*)(smr + PJ_B_OFF + cur*PJ_B_SZ);
        #pragma unroll
        for(int ks=0;ks<4;ks++){
            u32 af[4];
            const bf16* ar = As + (w*16 + g)*72 + ks*16 + 2*tig;
            af[0] = *(const u32*)ar;
            af[1] = *(const u32*)(ar + 8*72);
            af[2] = *(const u32*)(ar + 8);
            af[3] = *(const u32*)(ar + 8*72 + 8);
            #pragma unroll
            for(int bn=0;bn<8;bn++){
                const bf16* br = Bs + (bn*8 + g)*72 + ks*16 + 2*tig;
                u32 b0 = *(const u32*)br, b1 = *(const u32*)(br + 8);
                mma16816(acc[bn], af, b0, b1);
            }
        }
    }

    __syncthreads();
    float* smf = (float*)smr;   // [64 cols][132]
    {
        int rl = w*16 + g;
        #pragma unroll
        for(int bn=0;bn<8;bn++){
            int col = bn*8 + 2*tig;
            smf[col*132 + rl]         = acc[bn][0];
            smf[(col+1)*132 + rl]     = acc[bn][1];
            smf[col*132 + rl + 8]     = acc[bn][2];
            smf[(col+1)*132 + rl + 8] = acc[bn][3];
        }
    }
    __syncthreads();
    {
        int cc = t >> 2, q4 = t & 3;
        int c = c0 + cc;
        float scl = bn_scale[c] * rsqrtf(bn_var[c] + EPSV);
        float mu  = bn_mean[c];
        float bi  = bn_bias[c];
        float gm  = gamma[0];
        const float* xr = x   + ((size_t)(b*CC) + c)*HWN + m0 + q4*32;
        float* orow     = out + ((size_t)(b*CC) + c)*HWN + m0 + q4*32;
        #pragma unroll
        for(int q=0;q<8;q++){
            float4 xv = *(const float4*)(xr + q*4);
            float4 o;
            float v0 = smf[cc*132 + q4*32 + q*4 + 0];
            float v1 = smf[cc*132 + q4*32 + q*4 + 1];
            float v2 = smf[cc*132 + q4*32 + q*4 + 2];
            float v3 = smf[cc*132 + q4*32 + q*4 + 3];
            o.x = gm*fmaxf((v0-mu)*scl+bi, 0.f) + xv.x;
            o.y = gm*fmaxf((v1-mu)*scl+bi, 0.f) + xv.y;
            o.z = gm*fmaxf((v2-mu)*scl+bi, 0.f) + xv.z;
            o.w = gm*fmaxf((v3-mu)*scl+bi, 0.f) + xv.w;
            *(float4*)(orow + q*4) = o;
        }
    }
}

// ---------------- launch ----------------
extern "C" void kernel_launch(void* const* d_in, const int* in_sizes, int n_in,
                              void* d_out, int out_size){
    (void)in_sizes; (void)n_in; (void)out_size;
    const float* x        = (const float*)d_in[0];
    const float* Wq       = (const float*)d_in[1];
    const float* Wk       = (const float*)d_in[2];
    const float* Wv       = (const float*)d_in[3];
    const float* Wb1      = (const float*)d_in[4];
    const float* Wb2      = (const float*)d_in[5];
    const float* w_gb     = (const float*)d_in[6];
    const float* ge_w1    = (const float*)d_in[7];
    const float* ge_b1    = (const float*)d_in[8];
    const float* ge_w2    = (const float*)d_in[9];
    const float* ge_b2    = (const float*)d_in[10];
    const float* Wo       = (const float*)d_in[11];
    const float* bn_scale = (const float*)d_in[12];
    const float* bn_bias  = (const float*)d_in[13];
    const float* bn_mean  = (const float*)d_in[14];
    const float* bn_var   = (const float*)d_in[15];
    const float* gamma    = (const float*)d_in[16];
    float* out = (float*)d_out;

    cudaFuncSetAttribute(k_attn,   cudaFuncAttributeMaxDynamicSharedMemorySize, ATTN_SMEM);
    cudaFuncSetAttribute(k_projmm, cudaFuncAttributeMaxDynamicSharedMemorySize, PJ_SMEM);
    cudaFuncSetAttribute(k_final,  cudaFuncAttributeMaxDynamicSharedMemorySize, PJ_SMEM);

    k_mean  <<<dim3(CC/8, BB), 256>>>(x);
    k_gate  <<<BB, 256>>>(ge_w1, ge_b1, ge_w2, ge_b2);
    k_xpose <<<dim3(HWN/128, CC/32, BB), 128>>>(x);
    k_wprep <<<(BB*NO*CC + CC*CC)/256, 256>>>(Wq, Wk, Wb1, Wb2, Wv, Wo);
    k_projmm<<<dim3(HWN/128, NO/64, BB), 256, PJ_SMEM>>>();
    k_smooth<<<(BB*HWN*KCN)/256, 256>>>();
    k_attn  <<<dim3(HWN/64, BB), 256, ATTN_SMEM>>>(w_gb);
    k_final <<<dim3(HWN/128, CC/64, BB), 256, PJ_SMEM>>>(x, bn_scale, bn_bias,
                                                         bn_mean, bn_var, gamma, out);
}

// round 11
// speedup vs baseline: 1.0093x; 1.0093x over previous
#include <cuda_runtime.h>
#include <cuda_bf16.h>
#include <math.h>

#define BB 2
#define CC 256
#define HWN 4096
#define KCN 32
#define RDN 16
#define NO 384
#define EPSV 1e-5f

typedef unsigned long long u64;
typedef unsigned int u32;
typedef __nv_bfloat16 bf16;

// ---------------- scratch ----------------
__device__ float g_mean[BB*CC];
__device__ float g_gate[BB*CC];
__device__ bf16  g_xb  [BB*HWN*CC];     // [b][m][c]
__device__ bf16  g_Wb  [BB*NO*CC];      // [b][o][c]  (gate folded into K rows)
__device__ bf16  g_Wob [CC*CC];         // [o][c]
__device__ bf16  g_Qb  [BB*HWN*KCN];    // [b][m][k]
__device__ bf16  g_Kb  [BB*HWN*KCN];
__device__ float g_b1r [BB*HWN*KCN];    // [b][m][k] fp32 pre-smooth (relu'd)
__device__ float g_b2r [BB*HWN*KCN];
__device__ bf16  g_b1b [BB*HWN*KCN];    // smoothed
__device__ bf16  g_b2b [BB*HWN*KCN];
__device__ bf16  g_Vb  [BB*CC*HWN];     // [b][c][m]
__device__ bf16  g_ctxb[BB*HWN*CC];     // [b][n][c]

__device__ __forceinline__ float sigm(float x){
    return __fdividef(1.0f, 1.0f + __expf(-x));
}
__device__ __forceinline__ void cpa16(u32 dst, const void* src){
    asm volatile("cp.async.ca.shared.global [%0], [%1], 16;" :: "r"(dst), "l"(src));
}
__device__ __forceinline__ void cpa_commit(){ asm volatile("cp.async.commit_group;"); }
__device__ __forceinline__ u32 bf2(float lo, float hi){
    u32 r; asm("cvt.rn.bf16x2.f32 %0, %1, %2;" : "=r"(r) : "f"(hi), "f"(lo)); return r;
}
__device__ __forceinline__ void mma16816(float* c, const u32* a, u32 b0, u32 b1){
    asm("mma.sync.aligned.m16n8k16.row.col.f32.bf16.bf16.f32 "
        "{%0,%1,%2,%3}, {%4,%5,%6,%7}, {%8,%9}, {%0,%1,%2,%3};"
        : "+f"(c[0]),"+f"(c[1]),"+f"(c[2]),"+f"(c[3])
        : "r"(a[0]),"r"(a[1]),"r"(a[2]),"r"(a[3]), "r"(b0),"r"(b1));
}

// ---------------- 1) per-(b,c) spatial mean ----------------
__global__ void k_mean(const float* __restrict__ x){
    int b = blockIdx.y;
    int c = blockIdx.x*8 + (threadIdx.x>>5);
    int lane = threadIdx.x & 31;
    const float* p = x + ((size_t)(b*CC + c))*HWN;
    float s = 0.f;
    for(int i=lane;i<HWN;i+=32) s += p[i];
    #pragma unroll
    for(int o=16;o;o>>=1) s += __shfl_xor_sync(0xffffffffu, s, o);
    if(lane==0) g_mean[b*CC+c] = s * (1.0f/HWN);
}

// ---------------- 2) GatherExcite MLP -> sigmoid gate ----------------
__global__ void k_gate(const float* __restrict__ w1, const float* __restrict__ b1,
                       const float* __restrict__ w2, const float* __restrict__ b2){
    __shared__ float sm[CC];
    __shared__ float sg[RDN];
    int b = blockIdx.x, t = threadIdx.x;
    sm[t] = g_mean[b*CC + t];
    __syncthreads();
    if(t < RDN){
        float a = b1[t];
        for(int c=0;c<CC;c++) a += w1[t*CC + c]*sm[c];
        sg[t] = fmaxf(a, 0.f);
    }
    __syncthreads();
    float a = b2[t];
    #pragma unroll
    for(int r=0;r<RDN;r++) a += w2[t*RDN + r]*sg[r];
    g_gate[b*CC + t] = sigm(a);
}

// ---------------- 2b) x transpose+convert: [b][c][m] f32 -> [b][m][c] bf16 -------
__global__ void __launch_bounds__(128) k_xpose(const float* __restrict__ x){
    __shared__ float sm[32][129];
    int b = blockIdx.z, c0 = blockIdx.y*32, m0 = blockIdx.x*128;
    int t = threadIdx.x;
    #pragma unroll 4
    for(int ci=0; ci<32; ci++)
        sm[ci][t] = x[((size_t)(b*CC + c0 + ci))*HWN + m0 + t];
    __syncthreads();
    u32 pk[16];
    #pragma unroll
    for(int i=0;i<16;i++) pk[i] = bf2(sm[2*i][t], sm[2*i+1][t]);
    uint4* dst = (uint4*)(g_xb + ((size_t)(b*HWN) + m0 + t)*CC + c0);
    #pragma unroll
    for(int q=0;q<4;q++) dst[q] = ((uint4*)pk)[q];
}

// ---------------- 2c) weight prep: bf16 [o][c], gate folded ----------------
__global__ void k_wprep(const float* __restrict__ Wq, const float* __restrict__ Wk,
                        const float* __restrict__ Wb1, const float* __restrict__ Wb2,
                        const float* __restrict__ Wv, const float* __restrict__ Wo){
    int idx = blockIdx.x*256 + threadIdx.x;
    if(idx < BB*NO*CC){
        int c = idx & 255;
        int o = (idx >> 8) % NO;
        int b = idx / (NO*CC);
        float w;
        if(o < 32)       w = Wq [o*CC + c];
        else if(o < 64)  w = Wk [(o-32)*CC + c] * g_gate[b*CC + c];
        else if(o < 96)  w = Wb1[(o-64)*CC + c];
        else if(o < 128) w = Wb2[(o-96)*CC + c];
        else             w = Wv [(o-128)*CC + c];
        g_Wb[idx] = __float2bfloat16(w);
    } else {
        int j = idx - BB*NO*CC;   // CC*CC elems
        g_Wob[j] = __float2bfloat16(Wo[j]);
    }
}

// ---------------- 3) fused projections on HMMA: ALL 4 chunks prefetched --------
// smem: A 4x[128][72] bf16 (18432 ea) | B 4x[64][72] bf16 (9216 ea) = 110592 B
#define PJ_A_SZ  18432
#define PJ_B_OFF (4*PJ_A_SZ)
#define PJ_B_SZ  9216
#define PJ_SMEM  (PJ_B_OFF + 4*PJ_B_SZ)

__device__ __forceinline__ void pj_wait(int cc){
    if(cc==0)      asm volatile("cp.async.wait_group 3;" ::: "memory");
    else if(cc==1) asm volatile("cp.async.wait_group 2;" ::: "memory");
    else if(cc==2) asm volatile("cp.async.wait_group 1;" ::: "memory");
    else           asm volatile("cp.async.wait_group 0;" ::: "memory");
}

__global__ void __launch_bounds__(128,1) k_projmm(){
    extern __shared__ char smr[];
    const u32 sb = (u32)__cvta_generic_to_shared(smr);
    const int t    = threadIdx.x;
    const int w    = t >> 5;
    const int lane = t & 31;
    const int g    = lane >> 2;
    const int tig  = lane & 3;
    const int b    = blockIdx.z;
    const int yblk = blockIdx.y;         // 0:{Q,K} 1:{b1,b2} 2..5:V
    const int m0   = blockIdx.x*128;
    const int o0   = yblk*64;

    const bf16* asrc = g_xb + ((size_t)(b*HWN) + m0)*CC;
    const bf16* bsrc = g_Wb + ((size_t)(b*NO)  + o0)*CC;

    float acc[2][8][4];
    #pragma unroll
    for(int mf=0;mf<2;mf++)
        #pragma unroll
        for(int bn=0;bn<8;bn++)
            #pragma unroll
            for(int q=0;q<4;q++) acc[mf][bn][q]=0.f;

    // prefetch ALL 4 chunks as 4 groups
    #pragma unroll
    for(int cc=0; cc<4; cc++){
        #pragma unroll
        for(int u=0;u<8;u++){
            int ch = t + u*128;             // 1024: 128 rows x 8
            int row = ch>>3, j = ch&7;
            cpa16(sb + (u32)(cc*PJ_A_SZ + row*144 + j*16),
                  asrc + (size_t)row*CC + cc*64 + j*8);
        }
        #pragma unroll
        for(int u=0;u<4;u++){
            int ch = t + u*128;             // 512: 64 rows x 8
            int row = ch>>3, j = ch&7;
            cpa16(sb + (u32)(PJ_B_OFF + cc*PJ_B_SZ + row*144 + j*16),
                  bsrc + (size_t)row*CC + cc*64 + j*8);
        }
        cpa_commit();
    }

    #pragma unroll
    for(int cc=0; cc<4; cc++){
        pj_wait(cc);
        __syncthreads();
        const bf16* As = (const bf16*)(smr + cc*PJ_A_SZ);
        const bf16* Bs = (const bf16*)(smr + PJ_B_OFF + cc*PJ_B_SZ);
        #pragma unroll
        for(int ks=0;ks<4;ks++){
            u32 af[2][4];
            #pragma unroll
            for(int mf=0;mf<2;mf++){
                const bf16* ar = As + (w*32 + mf*16 + g)*72 + ks*16 + 2*tig;
                af[mf][0] = *(const u32*)ar;
                af[mf][1] = *(const u32*)(ar + 8*72);
                af[mf][2] = *(const u32*)(ar + 8);
                af[mf][3] = *(const u32*)(ar + 8*72 + 8);
            }
            #pragma unroll
            for(int bn=0;bn<8;bn++){
                const bf16* br = Bs + (bn*8 + g)*72 + ks*16 + 2*tig;
                u32 b0 = *(const u32*)br, b1 = *(const u32*)(br + 8);
                mma16816(acc[0][bn], af[0], b0, b1);
                mma16816(acc[1][bn], af[1], b0, b1);
            }
        }
    }

    if(yblk == 0){
        #pragma unroll
        for(int mf=0;mf<2;mf++){
            int r0g = m0 + w*32 + mf*16 + g;
            #pragma unroll
            for(int bn=0;bn<8;bn++){
                int o = bn*8 + 2*tig;
                bf16* base = (o<32) ? g_Qb : g_Kb;
                int oo = o & 31;
                *(u32*)(base + ((size_t)(b*HWN) + r0g    )*KCN + oo) = bf2(acc[mf][bn][0], acc[mf][bn][1]);
                *(u32*)(base + ((size_t)(b*HWN) + r0g + 8)*KCN + oo) = bf2(acc[mf][bn][2], acc[mf][bn][3]);
            }
        }
    } else if(yblk == 1){
        #pragma unroll
        for(int mf=0;mf<2;mf++){
            int r0g = m0 + w*32 + mf*16 + g;
            #pragma unroll
            for(int bn=0;bn<8;bn++){
                int o = bn*8 + 2*tig;
                float* base = (o<32) ? g_b1r : g_b2r;
                int oo = o & 31;
                float2 v0; v0.x = fmaxf(acc[mf][bn][0],0.f); v0.y = fmaxf(acc[mf][bn][1],0.f);
                float2 v1; v1.x = fmaxf(acc[mf][bn][2],0.f); v1.y = fmaxf(acc[mf][bn][3],0.f);
                *(float2*)(base + ((size_t)(b*HWN) + r0g    )*KCN + oo) = v0;
                *(float2*)(base + ((size_t)(b*HWN) + r0g + 8)*KCN + oo) = v1;
            }
        }
    } else {
        // V: transpose epilogue -> g_Vb[b][c][m] bf16
        __syncthreads();
        float* smf = (float*)smr;         // [64 cols][132]
        #pragma unroll
        for(int mf=0;mf<2;mf++){
            int rl = w*32 + mf*16 + g;
            #pragma unroll
            for(int bn=0;bn<8;bn++){
                int col = bn*8 + 2*tig;
                smf[col*132 + rl]         = acc[mf][bn][0];
                smf[(col+1)*132 + rl]     = acc[mf][bn][1];
                smf[col*132 + rl + 8]     = acc[mf][bn][2];
                smf[(col+1)*132 + rl + 8] = acc[mf][bn][3];
            }
        }
        __syncthreads();
        int cc = t >> 1, half = t & 1;
        int c = (yblk-2)*64 + cc;
        bf16* dst = g_Vb + ((size_t)(b*CC) + c)*HWN + m0 + half*64;
        u32 pk[32];
        #pragma unroll
        for(int j=0;j<32;j++)
            pk[j] = bf2(smf[cc*132 + half*64 + 2*j], smf[cc*132 + half*64 + 2*j + 1]);
        #pragma unroll
        for(int q=0;q<8;q++) ((uint4*)dst)[q] = ((uint4*)pk)[q];
    }
}

// ---------------- 5) 3-tap box smoothing ([m][k] layout) ----------------
__global__ void k_smooth(){
    int idx = blockIdx.x*256 + threadIdx.x;
    int k = idx & 31;
    int m = (idx >> 5) & (HWN-1);
    int b = idx >> 17;
    size_t base = ((size_t)(b*HWN) + m)*KCN + k;
    float a1 = g_b1r[base], a2 = g_b2r[base];
    if(m > 0)      { a1 += g_b1r[base-KCN]; a2 += g_b2r[base-KCN]; }
    if(m < HWN-1)  { a1 += g_b1r[base+KCN]; a2 += g_b2r[base+KCN]; }
    g_b1b[base] = __float2bfloat16(a1);
    g_b2b[base] = __float2bfloat16(a2);
}

// ---------------- 6) fused attention: HMMA, 3-buffer ring, 1 barrier/tile ------
// smem: V 3x[256][72 bf16] | K 3x[64][40 bf16] | B2 3x[64][40 bf16]
#define VT_SZ    36864
#define KT_OFF   (3*VT_SZ)
#define KT_SZ    5120
#define B2_OFF   (KT_OFF + 3*KT_SZ)
#define B2_SZ    5120
#define ATTN_SMEM (B2_OFF + 3*B2_SZ)

__device__ __forceinline__ void attn_prefetch(u32 sb, int t, int b, int key0, int buf){
    #pragma unroll
    for(int u=0;u<8;u++){
        int ch = t + u*256;                 // 2048: 256 rows x 8
        int row = ch>>3, j = ch&7;
        cpa16(sb + (u32)(buf*VT_SZ + row*144 + j*16),
              g_Vb + ((size_t)b*CC + row)*HWN + key0 + j*8);
    }
    {
        int key = t>>2, j = t&3;            // 256: 64 rows x 4
        cpa16(sb + (u32)(KT_OFF + buf*KT_SZ + key*80 + j*16),
              g_Kb + ((size_t)(b*HWN) + key0 + key)*KCN + j*8);
        cpa16(sb + (u32)(B2_OFF + buf*B2_SZ + key*80 + j*16),
              g_b2b + ((size_t)(b*HWN) + key0 + key)*KCN + j*8);
    }
}

__global__ void __launch_bounds__(256,1) k_attn(const float* __restrict__ wgb){
    extern __shared__ char smr[];
    const u32 sb = (u32)__cvta_generic_to_shared(smr);
    const int t    = threadIdx.x;
    const int w    = t >> 5;
    const int wm   = w & 3;        // row-block warp
    const int kh   = w >> 2;       // key half (0: keys 0-31, 1: keys 32-63 of tile)
    const int lane = t & 31;
    const int g    = lane >> 2;
    const int tig  = lane & 3;
    const int b    = blockIdx.y;
    const int row0 = blockIdx.x*64 + wm*16;

    attn_prefetch(sb, t, b, 0,  0); cpa_commit();
    attn_prefetch(sb, t, b, 64, 1); cpa_commit();

    u32 qf[2][4], b1f[2][4];
    {
        const bf16* q0 = g_Qb  + ((size_t)(b*HWN) + row0 + g)*KCN;
        const bf16* c0 = g_b1b + ((size_t)(b*HWN) + row0 + g)*KCN;
        #pragma unroll
        for(int ks=0;ks<2;ks++){
            qf[ks][0]  = *(const u32*)(q0 + ks*16 + 2*tig);
            qf[ks][1]  = *(const u32*)(q0 + 8*KCN + ks*16 + 2*tig);
            qf[ks][2]  = *(const u32*)(q0 + ks*16 + 2*tig + 8);
            qf[ks][3]  = *(const u32*)(q0 + 8*KCN + ks*16 + 2*tig + 8);
            b1f[ks][0] = *(const u32*)(c0 + ks*16 + 2*tig);
            b1f[ks][1] = *(const u32*)(c0 + 8*KCN + ks*16 + 2*tig);
            b1f[ks][2] = *(const u32*)(c0 + ks*16 + 2*tig + 8);
            b1f[ks][3] = *(const u32*)(c0 + 8*KCN + ks*16 + 2*tig + 8);
        }
    }

    float pv[32][4];
    #pragma unroll
    for(int i=0;i<32;i++){ pv[i][0]=0.f; pv[i][1]=0.f; pv[i][2]=0.f; pv[i][3]=0.f; }
    float ls0 = 0.f, ls1 = 0.f;
    const float cgb = wgb[0] * (1.0f/9.0f);

    int cur = 0;
    for(int tile=0; tile<HWN/64; tile++){
        if(tile < HWN/64 - 1)
            asm volatile("cp.async.wait_group 1;" ::: "memory");
        else
            asm volatile("cp.async.wait_group 0;" ::: "memory");
        __syncthreads();   // tile data visible AND all warps done reading buf (tile-1)%3

        if(tile+2 < HWN/64){
            int pf = cur + 2; if(pf >= 3) pf -= 3;
            attn_prefetch(sb, t, b, (tile+2)*64, pf);
            cpa_commit();
        }

        const bf16* Ks  = (const bf16*)(smr + KT_OFF + cur*KT_SZ);
        const bf16* B2s = (const bf16*)(smr + B2_OFF + cur*B2_SZ);
        const bf16* Vs  = (const bf16*)(smr + cur*VT_SZ);

        u32 pa[4][2];
        #pragma unroll
        for(int nt=0; nt<4; nt++){
            int gnt = kh*4 + nt;
            float sa[4] = {0.f,0.f,0.f,0.f};
            float pl[4] = {0.f,0.f,0.f,0.f};
            const bf16* kr = Ks  + (gnt*8 + g)*40;
            const bf16* br = B2s + (gnt*8 + g)*40;
            #pragma unroll
            for(int ks=0;ks<2;ks++){
                u32 k0  = *(const u32*)(kr + ks*16 + 2*tig);
                u32 k1  = *(const u32*)(kr + ks*16 + 2*tig + 8);
                u32 bb0 = *(const u32*)(br + ks*16 + 2*tig);
                u32 bb1 = *(const u32*)(br + ks*16 + 2*tig + 8);
                mma16816(sa, qf[ks],  k0,  k1);
                mma16816(pl, b1f[ks], bb0, bb1);
            }
            float e0 = __expf(sa[0] * sigm(cgb*pl[0]));
            float e1 = __expf(sa[1] * sigm(cgb*pl[1]));
            float e2 = __expf(sa[2] * sigm(cgb*pl[2]));
            float e3 = __expf(sa[3] * sigm(cgb*pl[3]));
            ls0 += e0 + e1;
            ls1 += e2 + e3;
            pa[nt][0] = bf2(e0, e1);
            pa[nt][1] = bf2(e2, e3);
        }

        #pragma unroll
        for(int cnt=0; cnt<32; cnt++){
            const bf16* vr = Vs + (cnt*8 + g)*72 + kh*32;
            #pragma unroll
            for(int ks=0;ks<2;ks++){
                u32 v0 = *(const u32*)(vr + 16*ks + 2*tig);
                u32 v1 = *(const u32*)(vr + 16*ks + 2*tig + 8);
                u32 af[4] = { pa[2*ks][0], pa[2*ks][1], pa[2*ks+1][0], pa[2*ks+1][1] };
                mma16816(pv[cnt], af, v0, v1);
            }
        }

        cur++; if(cur == 3) cur = 0;
    }

    #pragma unroll
    for(int o=1;o<4;o<<=1){
        ls0 += __shfl_xor_sync(0xffffffffu, ls0, o);
        ls1 += __shfl_xor_sync(0xffffffffu, ls1, o);
    }

    __syncthreads();
    float* smf = (float*)smr;       // [4*32][131]
    if(kh == 1){
        float* dst = smf + (size_t)(wm*32 + lane)*131;
        #pragma unroll
        for(int cnt=0;cnt<32;cnt++){
            dst[cnt*4+0] = pv[cnt][0]; dst[cnt*4+1] = pv[cnt][1];
            dst[cnt*4+2] = pv[cnt][2]; dst[cnt*4+3] = pv[cnt][3];
        }
        dst[128] = ls0; dst[129] = ls1;
    }
    __syncthreads();
    if(kh == 0){
        const float* src = smf + (size_t)(wm*32 + lane)*131;
        #pragma unroll
        for(int cnt=0;cnt<32;cnt++){
            pv[cnt][0] += src[cnt*4+0]; pv[cnt][1] += src[cnt*4+1];
            pv[cnt][2] += src[cnt*4+2]; pv[cnt][3] += src[cnt*4+3];
        }
        ls0 += src[128]; ls1 += src[129];

        float rl0 = __fdividef(1.0f, ls0);
        float rl1 = __fdividef(1.0f, ls1);
        u32* d0 = (u32*)(g_ctxb + ((size_t)(b*HWN) + row0 + g    )*CC);
        u32* d8 = (u32*)(g_ctxb + ((size_t)(b*HWN) + row0 + g + 8)*CC);
        #pragma unroll
        for(int cnt=0; cnt<32; cnt++){
            d0[cnt*4 + tig] = bf2(pv[cnt][0]*rl0, pv[cnt][1]*rl0);
            d8[cnt*4 + tig] = bf2(pv[cnt][2]*rl1, pv[cnt][3]*rl1);
        }
    }
}

// ---------------- 7) output projection (HMMA, full prefetch) + BN + residual ----
__global__ void __launch_bounds__(128,1) k_final(
    const float* __restrict__ x,
    const float* __restrict__ bn_scale, const float* __restrict__ bn_bias,
    const float* __restrict__ bn_mean, const float* __restrict__ bn_var,
    const float* __restrict__ gamma, float* __restrict__ out)
{
    extern __shared__ char smr[];
    const u32 sb = (u32)__cvta_generic_to_shared(smr);
    const int t    = threadIdx.x;
    const int w    = t >> 5;
    const int lane = t & 31;
    const int g    = lane >> 2;
    const int tig  = lane & 3;
    const int b    = blockIdx.z;
    const int c0   = blockIdx.y*64;
    const int m0   = blockIdx.x*128;

    const bf16* asrc = g_ctxb + ((size_t)(b*HWN) + m0)*CC;
    const bf16* bsrc = g_Wob + (size_t)c0*CC;

    float acc[2][8][4];
    #pragma unroll
    for(int mf=0;mf<2;mf++)
        #pragma unroll
        for(int bn=0;bn<8;bn++)
            #pragma unroll
            for(int q=0;q<4;q++) acc[mf][bn][q]=0.f;

    #pragma unroll
    for(int cc=0; cc<4; cc++){
        #pragma unroll
        for(int u=0;u<8;u++){
            int ch = t + u*128;
            int row = ch>>3, j = ch&7;
            cpa16(sb + (u32)(cc*PJ_A_SZ + row*144 + j*16),
                  asrc + (size_t)row*CC + cc*64 + j*8);
        }
        #pragma unroll
        for(int u=0;u<4;u++){
            int ch = t + u*128;
            int row = ch>>3, j = ch&7;
            cpa16(sb + (u32)(PJ_B_OFF + cc*PJ_B_SZ + row*144 + j*16),
                  bsrc + (size_t)row*CC + cc*64 + j*8);
        }
        cpa_commit();
    }

    #pragma unroll
    for(int cc=0; cc<4; cc++){
        pj_wait(cc);
        __syncthreads();
        const bf16* As = (const bf16*)(smr + cc*PJ_A_SZ);
        const bf16* Bs = (const bf16*)(smr + PJ_B_OFF + cc*PJ_B_SZ);
        #pragma unroll
        for(int ks=0;ks<4;ks++){
            u32 af[2][4];
            #pragma unroll
            for(int mf=0;mf<2;mf++){
                const bf16* ar = As + (w*32 + mf*16 + g)*72 + ks*16 + 2*tig;
                af[mf][0] = *(const u32*)ar;
                af[mf][1] = *(const u32*)(ar + 8*72);
                af[mf][2] = *(const u32*)(ar + 8);
                af[mf][3] = *(const u32*)(ar + 8*72 + 8);
            }
            #pragma unroll
            for(int bn=0;bn<8;bn++){
                const bf16* br = Bs + (bn*8 + g)*72 + ks*16 + 2*tig;
                u32 b0 = *(const u32*)br, b1 = *(const u32*)(br + 8);
                mma16816(acc[0][bn], af[0], b0, b1);
                mma16816(acc[1][bn], af[1], b0, b1);
            }
        }
    }

    __syncthreads();
    float* smf = (float*)smr;   // [64 cols][132]
    #pragma unroll
    for(int mf=0;mf<2;mf++){
        int rl = w*32 + mf*16 + g;
        #pragma unroll
        for(int bn=0;bn<8;bn++){
            int col = bn*8 + 2*tig;
            smf[col*132 + rl]         = acc[mf][bn][0];
            smf[(col+1)*132 + rl]     = acc[mf][bn][1];
            smf[col*132 + rl + 8]     = acc[mf][bn][2];
            smf[(col+1)*132 + rl + 8] = acc[mf][bn][3];
        }
    }
    __syncthreads();
    {
        int cc = t >> 1, half = t & 1;
        int c = c0 + cc;
        float scl = bn_scale[c] * rsqrtf(bn_var[c] + EPSV);
        float mu  = bn_mean[c];
        float bi  = bn_bias[c];
        float gm  = gamma[0];
        const float* xr = x   + ((size_t)(b*CC) + c)*HWN + m0 + half*64;
        float* orow     = out + ((size_t)(b*CC) + c)*HWN + m0 + half*64;
        #pragma unroll
        for(int q=0;q<16;q++){
            float4 xv = *(const float4*)(xr + q*4);
            float4 o;
            float v0 = smf[cc*132 + half*64 + q*4 + 0];
            float v1 = smf[cc*132 + half*64 + q*4 + 1];
            float v2 = smf[cc*132 + half*64 + q*4 + 2];
            float v3 = smf[cc*132 + half*64 + q*4 + 3];
            o.x = gm*fmaxf((v0-mu)*scl+bi, 0.f) + xv.x;
            o.y = gm*fmaxf((v1-mu)*scl+bi, 0.f) + xv.y;
            o.z = gm*fmaxf((v2-mu)*scl+bi, 0.f) + xv.z;
            o.w = gm*fmaxf((v3-mu)*scl+bi, 0.f) + xv.w;
            *(float4*)(orow + q*4) = o;
        }
    }
}

// ---------------- launch ----------------
extern "C" void kernel_launch(void* const* d_in, const int* in_sizes, int n_in,
                              void* d_out, int out_size){
    (void)in_sizes; (void)n_in; (void)out_size;
    const float* x        = (const float*)d_in[0];
    const float* Wq       = (const float*)d_in[1];
    const float* Wk       = (const float*)d_in[2];
    const float* Wv       = (const float*)d_in[3];
    const float* Wb1      = (const float*)d_in[4];
    const float* Wb2      = (const float*)d_in[5];
    const float* w_gb     = (const float*)d_in[6];
    const float* ge_w1    = (const float*)d_in[7];
    const float* ge_b1    = (const float*)d_in[8];
    const float* ge_w2    = (const float*)d_in[9];
    const float* ge_b2    = (const float*)d_in[10];
    const float* Wo       = (const float*)d_in[11];
    const float* bn_scale = (const float*)d_in[12];
    const float* bn_bias  = (const float*)d_in[13];
    const float* bn_mean  = (const float*)d_in[14];
    const float* bn_var   = (const float*)d_in[15];
    const float* gamma    = (const float*)d_in[16];
    float* out = (float*)d_out;

    cudaFuncSetAttribute(k_attn,   cudaFuncAttributeMaxDynamicSharedMemorySize, ATTN_SMEM);
    cudaFuncSetAttribute(k_projmm, cudaFuncAttributeMaxDynamicSharedMemorySize, PJ_SMEM);
    cudaFuncSetAttribute(k_final,  cudaFuncAttributeMaxDynamicSharedMemorySize, PJ_SMEM);

    k_mean  <<<dim3(CC/8, BB), 256>>>(x);
    k_gate  <<<BB, 256>>>(ge_w1, ge_b1, ge_w2, ge_b2);
    k_xpose <<<dim3(HWN/128, CC/32, BB), 128>>>(x);
    k_wprep <<<(BB*NO*CC + CC*CC)/256, 256>>>(Wq, Wk, Wb1, Wb2, Wv, Wo);
    k_projmm<<<dim3(HWN/128, NO/64, BB), 128, PJ_SMEM>>>();
    k_smooth<<<(BB*HWN*KCN)/256, 256>>>();
    k_attn  <<<dim3(HWN/64, BB), 256, ATTN_SMEM>>>(w_gb);
    k_final <<<dim3(HWN/128, CC/64, BB), 128, PJ_SMEM>>>(x, bn_scale, bn_bias,
                                                         bn_mean, bn_var, gamma, out);
}

// round 12
// speedup vs baseline: 1.0827x; 1.0727x over previous
#include <cuda_runtime.h>
#include <cuda_bf16.h>
#include <math.h>

#define BB 2
#define CC 256
#define HWN 4096
#define KCN 32
#define RDN 16
#define NO 384
#define EPSV 1e-5f

typedef unsigned long long u64;
typedef unsigned int u32;
typedef __nv_bfloat16 bf16;

// ---------------- scratch ----------------
__device__ float g_mean[BB*CC];
__device__ float g_gate[BB*CC];
__device__ bf16  g_xb  [BB*HWN*CC];     // [b][m][c]
__device__ bf16  g_Wb  [BB*NO*CC];      // [b][o][c]  (gate folded into K rows)
__device__ bf16  g_Wob [CC*CC];         // [o][c]
__device__ bf16  g_Qb  [BB*HWN*KCN];    // [b][m][k]
__device__ bf16  g_Kb  [BB*HWN*KCN];
__device__ float g_b1r [BB*HWN*KCN];    // [b][m][k] fp32 pre-smooth (relu'd)
__device__ float g_b2r [BB*HWN*KCN];
__device__ bf16  g_b1b [BB*HWN*KCN];    // smoothed
__device__ bf16  g_b2b [BB*HWN*KCN];
__device__ bf16  g_Vb  [BB*CC*HWN];     // [b][c][m]

__device__ __forceinline__ float sigm(float x){
    return __fdividef(1.0f, 1.0f + __expf(-x));
}
__device__ __forceinline__ void cpa16(u32 dst, const void* src){
    asm volatile("cp.async.ca.shared.global [%0], [%1], 16;" :: "r"(dst), "l"(src));
}
__device__ __forceinline__ void cpa_commit(){ asm volatile("cp.async.commit_group;"); }
__device__ __forceinline__ u32 bf2(float lo, float hi){
    u32 r; asm("cvt.rn.bf16x2.f32 %0, %1, %2;" : "=r"(r) : "f"(hi), "f"(lo)); return r;
}
__device__ __forceinline__ void mma16816(float* c, const u32* a, u32 b0, u32 b1){
    asm("mma.sync.aligned.m16n8k16.row.col.f32.bf16.bf16.f32 "
        "{%0,%1,%2,%3}, {%4,%5,%6,%7}, {%8,%9}, {%0,%1,%2,%3};"
        : "+f"(c[0]),"+f"(c[1]),"+f"(c[2]),"+f"(c[3])
        : "r"(a[0]),"r"(a[1]),"r"(a[2]),"r"(a[3]), "r"(b0),"r"(b1));
}

// ---------------- 1) per-(b,c) spatial mean ----------------
__global__ void k_mean(const float* __restrict__ x){
    int b = blockIdx.y;
    int c = blockIdx.x*8 + (threadIdx.x>>5);
    int lane = threadIdx.x & 31;
    const float* p = x + ((size_t)(b*CC + c))*HWN;
    float s = 0.f;
    for(int i=lane;i<HWN;i+=32) s += p[i];
    #pragma unroll
    for(int o=16;o;o>>=1) s += __shfl_xor_sync(0xffffffffu, s, o);
    if(lane==0) g_mean[b*CC+c] = s * (1.0f/HWN);
}

// ---------------- 2) GatherExcite MLP -> sigmoid gate ----------------
__global__ void k_gate(const float* __restrict__ w1, const float* __restrict__ b1,
                       const float* __restrict__ w2, const float* __restrict__ b2){
    __shared__ float sm[CC];
    __shared__ float sg[RDN];
    int b = blockIdx.x, t = threadIdx.x;
    sm[t] = g_mean[b*CC + t];
    __syncthreads();
    if(t < RDN){
        float a = b1[t];
        for(int c=0;c<CC;c++) a += w1[t*CC + c]*sm[c];
        sg[t] = fmaxf(a, 0.f);
    }
    __syncthreads();
    float a = b2[t];
    #pragma unroll
    for(int r=0;r<RDN;r++) a += w2[t*RDN + r]*sg[r];
    g_gate[b*CC + t] = sigm(a);
}

// ---------------- 2b) x transpose+convert: [b][c][m] f32 -> [b][m][c] bf16 -------
__global__ void __launch_bounds__(128) k_xpose(const float* __restrict__ x){
    __shared__ float sm[32][129];
    int b = blockIdx.z, c0 = blockIdx.y*32, m0 = blockIdx.x*128;
    int t = threadIdx.x;
    #pragma unroll 4
    for(int ci=0; ci<32; ci++)
        sm[ci][t] = x[((size_t)(b*CC + c0 + ci))*HWN + m0 + t];
    __syncthreads();
    u32 pk[16];
    #pragma unroll
    for(int i=0;i<16;i++) pk[i] = bf2(sm[2*i][t], sm[2*i+1][t]);
    uint4* dst = (uint4*)(g_xb + ((size_t)(b*HWN) + m0 + t)*CC + c0);
    #pragma unroll
    for(int q=0;q<4;q++) dst[q] = ((uint4*)pk)[q];
}

// ---------------- 2c) weight prep: bf16 [o][c], gate folded ----------------
__global__ void k_wprep(const float* __restrict__ Wq, const float* __restrict__ Wk,
                        const float* __restrict__ Wb1, const float* __restrict__ Wb2,
                        const float* __restrict__ Wv, const float* __restrict__ Wo){
    int idx = blockIdx.x*256 + threadIdx.x;
    if(idx < BB*NO*CC){
        int c = idx & 255;
        int o = (idx >> 8) % NO;
        int b = idx / (NO*CC);
        float w;
        if(o < 32)       w = Wq [o*CC + c];
        else if(o < 64)  w = Wk [(o-32)*CC + c] * g_gate[b*CC + c];
        else if(o < 96)  w = Wb1[(o-64)*CC + c];
        else if(o < 128) w = Wb2[(o-96)*CC + c];
        else             w = Wv [(o-128)*CC + c];
        g_Wb[idx] = __float2bfloat16(w);
    } else {
        int j = idx - BB*NO*CC;   // CC*CC elems
        g_Wob[j] = __float2bfloat16(Wo[j]);
    }
}

// ---------------- 3) fused projections on HMMA (R9 config: 128 thr, 2-buf) -----
// smem: A 2x[128][72] bf16 (18432 ea) | B 2x[64][72] bf16 (9216 ea)
#define PJ_A_SZ  18432
#define PJ_B_OFF 36864
#define PJ_B_SZ  9216
#define PJ_SMEM  55296

__global__ void __launch_bounds__(128,1) k_projmm(){
    extern __shared__ char smr[];
    const u32 sb = (u32)__cvta_generic_to_shared(smr);
    const int t    = threadIdx.x;
    const int w    = t >> 5;
    const int lane = t & 31;
    const int g    = lane >> 2;
    const int tig  = lane & 3;
    const int b    = blockIdx.z;
    const int yblk = blockIdx.y;         // 0:{Q,K} 1:{b1,b2} 2..5:V
    const int m0   = blockIdx.x*128;
    const int o0   = yblk*64;

    const bf16* asrc = g_xb + ((size_t)(b*HWN) + m0)*CC;
    const bf16* bsrc = g_Wb + ((size_t)(b*NO)  + o0)*CC;

    float acc[2][8][4];
    #pragma unroll
    for(int mf=0;mf<2;mf++)
        #pragma unroll
        for(int bn=0;bn<8;bn++)
            #pragma unroll
            for(int q=0;q<4;q++) acc[mf][bn][q]=0.f;

    {
        #pragma unroll
        for(int u=0;u<8;u++){
            int ch = t + u*128;
            int row = ch>>3, j = ch&7;
            cpa16(sb + (u32)(row*144 + j*16), asrc + (size_t)row*CC + j*8);
        }
        #pragma unroll
        for(int u=0;u<4;u++){
            int ch = t + u*128;
            int row = ch>>3, j = ch&7;
            cpa16(sb + PJ_B_OFF + (u32)(row*144 + j*16), bsrc + (size_t)row*CC + j*8);
        }
        cpa_commit();
    }

    for(int cc=0; cc<4; cc++){
        const int cur = cc & 1;
        __syncthreads();
        if(cc+1 < 4){
            const int nb = 1-cur;
            #pragma unroll
            for(int u=0;u<8;u++){
                int ch = t + u*128;
                int row = ch>>3, j = ch&7;
                cpa16(sb + (u32)(nb*PJ_A_SZ + row*144 + j*16),
                      asrc + (size_t)row*CC + (cc+1)*64 + j*8);
            }
            #pragma unroll
            for(int u=0;u<4;u++){
                int ch = t + u*128;
                int row = ch>>3, j = ch&7;
                cpa16(sb + (u32)(PJ_B_OFF + nb*PJ_B_SZ + row*144 + j*16),
                      bsrc + (size_t)row*CC + (cc+1)*64 + j*8);
            }
            cpa_commit();
            asm volatile("cp.async.wait_group 1;" ::: "memory");
        } else {
            asm volatile("cp.async.wait_group 0;" ::: "memory");
        }
        __syncthreads();

        const bf16* As = (const bf16*)(smr + cur*PJ_A_SZ);
        const bf16* Bs = (const bf16*)(smr + PJ_B_OFF + cur*PJ_B_SZ);
        #pragma unroll
        for(int ks=0;ks<4;ks++){
            u32 af[2][4];
            #pragma unroll
            for(int mf=0;mf<2;mf++){
                const bf16* ar = As + (w*32 + mf*16 + g)*72 + ks*16 + 2*tig;
                af[mf][0] = *(const u32*)ar;
                af[mf][1] = *(const u32*)(ar + 8*72);
                af[mf][2] = *(const u32*)(ar + 8);
                af[mf][3] = *(const u32*)(ar + 8*72 + 8);
            }
            #pragma unroll
            for(int bn=0;bn<8;bn++){
                const bf16* br = Bs + (bn*8 + g)*72 + ks*16 + 2*tig;
                u32 b0 = *(const u32*)br, b1 = *(const u32*)(br + 8);
                mma16816(acc[0][bn], af[0], b0, b1);
                mma16816(acc[1][bn], af[1], b0, b1);
            }
        }
    }

    if(yblk == 0){
        #pragma unroll
        for(int mf=0;mf<2;mf++){
            int r0g = m0 + w*32 + mf*16 + g;
            #pragma unroll
            for(int bn=0;bn<8;bn++){
                int o = bn*8 + 2*tig;
                bf16* base = (o<32) ? g_Qb : g_Kb;
                int oo = o & 31;
                *(u32*)(base + ((size_t)(b*HWN) + r0g    )*KCN + oo) = bf2(acc[mf][bn][0], acc[mf][bn][1]);
                *(u32*)(base + ((size_t)(b*HWN) + r0g + 8)*KCN + oo) = bf2(acc[mf][bn][2], acc[mf][bn][3]);
            }
        }
    } else if(yblk == 1){
        #pragma unroll
        for(int mf=0;mf<2;mf++){
            int r0g = m0 + w*32 + mf*16 + g;
            #pragma unroll
            for(int bn=0;bn<8;bn++){
                int o = bn*8 + 2*tig;
                float* base = (o<32) ? g_b1r : g_b2r;
                int oo = o & 31;
                float2 v0; v0.x = fmaxf(acc[mf][bn][0],0.f); v0.y = fmaxf(acc[mf][bn][1],0.f);
                float2 v1; v1.x = fmaxf(acc[mf][bn][2],0.f); v1.y = fmaxf(acc[mf][bn][3],0.f);
                *(float2*)(base + ((size_t)(b*HWN) + r0g    )*KCN + oo) = v0;
                *(float2*)(base + ((size_t)(b*HWN) + r0g + 8)*KCN + oo) = v1;
            }
        }
    } else {
        __syncthreads();
        float* smf = (float*)smr;         // [64 cols][132]
        #pragma unroll
        for(int mf=0;mf<2;mf++){
            int rl = w*32 + mf*16 + g;
            #pragma unroll
            for(int bn=0;bn<8;bn++){
                int col = bn*8 + 2*tig;
                smf[col*132 + rl]         = acc[mf][bn][0];
                smf[(col+1)*132 + rl]     = acc[mf][bn][1];
                smf[col*132 + rl + 8]     = acc[mf][bn][2];
                smf[(col+1)*132 + rl + 8] = acc[mf][bn][3];
            }
        }
        __syncthreads();
        int cc = t >> 1, half = t & 1;
        int c = (yblk-2)*64 + cc;
        bf16* dst = g_Vb + ((size_t)(b*CC) + c)*HWN + m0 + half*64;
        u32 pk[32];
        #pragma unroll
        for(int j=0;j<32;j++)
            pk[j] = bf2(smf[cc*132 + half*64 + 2*j], smf[cc*132 + half*64 + 2*j + 1]);
        #pragma unroll
        for(int q=0;q<8;q++) ((uint4*)dst)[q] = ((uint4*)pk)[q];
    }
}

// ---------------- 5) 3-tap box smoothing ([m][k] layout) ----------------
__global__ void k_smooth(){
    int idx = blockIdx.x*256 + threadIdx.x;
    int k = idx & 31;
    int m = (idx >> 5) & (HWN-1);
    int b = idx >> 17;
    size_t base = ((size_t)(b*HWN) + m)*KCN + k;
    float a1 = g_b1r[base], a2 = g_b2r[base];
    if(m > 0)      { a1 += g_b1r[base-KCN]; a2 += g_b2r[base-KCN]; }
    if(m < HWN-1)  { a1 += g_b1r[base+KCN]; a2 += g_b2r[base+KCN]; }
    g_b1b[base] = __float2bfloat16(a1);
    g_b2b[base] = __float2bfloat16(a2);
}

// ---------------- 6) fused attention + output projection + BN + residual ------
// mainloop smem (R9 2-buf): V 2x[256][72] | K 2x[64][40] | B2 2x[64][40] = 94208
#define VT_SZ    36864
#define KT_OFF   73728
#define KT_SZ    5120
#define B2_OFF   83968
#define B2_SZ    5120
// epilogue smem (reuses dead mainloop regions; all offsets disjoint from live data)
#define SMF_OFF  0            // f32 combine [128][131] = 67072  (dead after combine)
#define CTX_OFF  67584        // bf16 [64][264] = 33792          (live all chunks)
#define TR_OFF   101376       // f32 [64][68]  = 17408
#define WO0_OFF  118784       // bf16 [64][264] = 33792 per chunk
#define WO1_OFF  152576
#define WO2_OFF  0            // overlaps SMF (dead), committed post-combine
#define WO3_OFF  33792
#define WO_PITCH 264
#define ATTN_SMEM 186368

__device__ __forceinline__ void attn_prefetch(u32 sb, int t, int b, int key0, int buf){
    #pragma unroll
    for(int u=0;u<8;u++){
        int ch = t + u*256;                 // 2048: 256 rows x 8
        int row = ch>>3, j = ch&7;
        cpa16(sb + (u32)(buf*VT_SZ + row*144 + j*16),
              g_Vb + ((size_t)b*CC + row)*HWN + key0 + j*8);
    }
    {
        int key = t>>2, j = t&3;            // 256: 64 rows x 4
        cpa16(sb + (u32)(KT_OFF + buf*KT_SZ + key*80 + j*16),
              g_Kb + ((size_t)(b*HWN) + key0 + key)*KCN + j*8);
        cpa16(sb + (u32)(B2_OFF + buf*B2_SZ + key*80 + j*16),
              g_b2b + ((size_t)(b*HWN) + key0 + key)*KCN + j*8);
    }
}

__device__ __forceinline__ void wo_prefetch(u32 sb, int t, int chunk, u32 off){
    const bf16* src = g_Wob + (size_t)(chunk*64)*CC;
    #pragma unroll
    for(int u=0;u<8;u++){
        int ch = t + u*256;                 // 2048: 64 rows x 32
        int row = ch>>5, j = ch&31;
        cpa16(sb + off + (u32)(row*(WO_PITCH*2) + j*16), src + (size_t)row*CC + j*8);
    }
    cpa_commit();
}

__global__ void __launch_bounds__(256,1) k_attn(
    const float* __restrict__ wgb, const float* __restrict__ x,
    const float* __restrict__ bn_scale, const float* __restrict__ bn_bias,
    const float* __restrict__ bn_mean, const float* __restrict__ bn_var,
    const float* __restrict__ gamma, float* __restrict__ out)
{
    extern __shared__ char smr[];
    const u32 sb = (u32)__cvta_generic_to_shared(smr);
    const int t    = threadIdx.x;
    const int w    = t >> 5;
    const int wm   = w & 3;        // row-block warp
    const int kh   = w >> 2;       // key half
    const int lane = t & 31;
    const int g    = lane >> 2;
    const int tig  = lane & 3;
    const int b    = blockIdx.y;
    const int n0   = blockIdx.x*64;
    const int row0 = n0 + wm*16;

    attn_prefetch(sb, t, b, 0, 0);
    cpa_commit();

    u32 qf[2][4], b1f[2][4];
    {
        const bf16* q0 = g_Qb  + ((size_t)(b*HWN) + row0 + g)*KCN;
        const bf16* c0 = g_b1b + ((size_t)(b*HWN) + row0 + g)*KCN;
        #pragma unroll
        for(int ks=0;ks<2;ks++){
            qf[ks][0]  = *(const u32*)(q0 + ks*16 + 2*tig);
            qf[ks][1]  = *(const u32*)(q0 + 8*KCN + ks*16 + 2*tig);
            qf[ks][2]  = *(const u32*)(q0 + ks*16 + 2*tig + 8);
            qf[ks][3]  = *(const u32*)(q0 + 8*KCN + ks*16 + 2*tig + 8);
            b1f[ks][0] = *(const u32*)(c0 + ks*16 + 2*tig);
            b1f[ks][1] = *(const u32*)(c0 + 8*KCN + ks*16 + 2*tig);
            b1f[ks][2] = *(const u32*)(c0 + ks*16 + 2*tig + 8);
            b1f[ks][3] = *(const u32*)(c0 + 8*KCN + ks*16 + 2*tig + 8);
        }
    }

    float pv[32][4];
    #pragma unroll
    for(int i=0;i<32;i++){ pv[i][0]=0.f; pv[i][1]=0.f; pv[i][2]=0.f; pv[i][3]=0.f; }
    float ls0 = 0.f, ls1 = 0.f;
    const float cgb = wgb[0] * (1.0f/9.0f);

    for(int tile=0; tile<HWN/64; tile++){
        const int cur = tile & 1;
        __syncthreads();
        if(tile+1 < HWN/64){
            attn_prefetch(sb, t, b, (tile+1)*64, 1-cur);
            cpa_commit();
            asm volatile("cp.async.wait_group 1;" ::: "memory");
        } else {
            asm volatile("cp.async.wait_group 0;" ::: "memory");
        }
        __syncthreads();

        const bf16* Ks  = (const bf16*)(smr + KT_OFF + cur*KT_SZ);
        const bf16* B2s = (const bf16*)(smr + B2_OFF + cur*B2_SZ);
        const bf16* Vs  = (const bf16*)(smr + cur*VT_SZ);

        u32 pa[4][2];
        #pragma unroll
        for(int nt=0; nt<4; nt++){
            int gnt = kh*4 + nt;
            float sa[4] = {0.f,0.f,0.f,0.f};
            float pl[4] = {0.f,0.f,0.f,0.f};
            const bf16* kr = Ks  + (gnt*8 + g)*40;
            const bf16* br = B2s + (gnt*8 + g)*40;
            #pragma unroll
            for(int ks=0;ks<2;ks++){
                u32 k0  = *(const u32*)(kr + ks*16 + 2*tig);
                u32 k1  = *(const u32*)(kr + ks*16 + 2*tig + 8);
                u32 bb0 = *(const u32*)(br + ks*16 + 2*tig);
                u32 bb1 = *(const u32*)(br + ks*16 + 2*tig + 8);
                mma16816(sa, qf[ks],  k0,  k1);
                mma16816(pl, b1f[ks], bb0, bb1);
            }
            float e0 = __expf(sa[0] * sigm(cgb*pl[0]));
            float e1 = __expf(sa[1] * sigm(cgb*pl[1]));
            float e2 = __expf(sa[2] * sigm(cgb*pl[2]));
            float e3 = __expf(sa[3] * sigm(cgb*pl[3]));
            ls0 += e0 + e1;
            ls1 += e2 + e3;
            pa[nt][0] = bf2(e0, e1);
            pa[nt][1] = bf2(e2, e3);
        }

        #pragma unroll
        for(int cnt=0; cnt<32; cnt++){
            const bf16* vr = Vs + (cnt*8 + g)*72 + kh*32;
            #pragma unroll
            for(int ks=0;ks<2;ks++){
                u32 v0 = *(const u32*)(vr + 16*ks + 2*tig);
                u32 v1 = *(const u32*)(vr + 16*ks + 2*tig + 8);
                u32 af[4] = { pa[2*ks][0], pa[2*ks][1], pa[2*ks+1][0], pa[2*ks+1][1] };
                mma16816(pv[cnt], af, v0, v1);
            }
        }
    }

    #pragma unroll
    for(int o=1;o<4;o<<=1){
        ls0 += __shfl_xor_sync(0xffffffffu, ls0, o);
        ls1 += __shfl_xor_sync(0xffffffffu, ls1, o);
    }

    // prefetch Wo chunks 0,1 (region beyond all mainloop/combine buffers)
    wo_prefetch(sb, t, 0, WO0_OFF);
    wo_prefetch(sb, t, 1, WO1_OFF);

    // ---- combine warp pairs (w and w+4) via smem ----
    __syncthreads();
    float* smf = (float*)(smr + SMF_OFF);   // [128][131]
    if(kh == 1){
        float* dst = smf + (size_t)(wm*32 + lane)*131;
        #pragma unroll
        for(int cnt=0;cnt<32;cnt++){
            dst[cnt*4+0] = pv[cnt][0]; dst[cnt*4+1] = pv[cnt][1];
            dst[cnt*4+2] = pv[cnt][2]; dst[cnt*4+3] = pv[cnt][3];
        }
        dst[128] = ls0; dst[129] = ls1;
    }
    __syncthreads();
    bf16* ctxs = (bf16*)(smr + CTX_OFF);    // [64][264]
    if(kh == 0){
        const float* src = smf + (size_t)(wm*32 + lane)*131;
        #pragma unroll
        for(int cnt=0;cnt<32;cnt++){
            pv[cnt][0] += src[cnt*4+0]; pv[cnt][1] += src[cnt*4+1];
            pv[cnt][2] += src[cnt*4+2]; pv[cnt][3] += src[cnt*4+3];
        }
        ls0 += src[128]; ls1 += src[129];
        float rl0 = __fdividef(1.0f, ls0);
        float rl1 = __fdividef(1.0f, ls1);
        int rl = wm*16 + g;
        #pragma unroll
        for(int cnt=0; cnt<32; cnt++){
            *(u32*)(ctxs + (size_t)rl*264     + cnt*8 + 2*tig) = bf2(pv[cnt][0]*rl0, pv[cnt][1]*rl0);
            *(u32*)(ctxs + (size_t)(rl+8)*264 + cnt*8 + 2*tig) = bf2(pv[cnt][2]*rl1, pv[cnt][3]*rl1);
        }
    }
    __syncthreads();   // ctx ready; smf dead -> WO2/WO3 regions safe
    wo_prefetch(sb, t, 2, WO2_OFF);
    wo_prefetch(sb, t, 3, WO3_OFF);

    // ---- fused output projection + BN + ReLU + residual ----
    const u32 wo_off[4] = {WO0_OFF, WO1_OFF, WO2_OFF, WO3_OFF};
    float* tr = (float*)(smr + TR_OFF);     // [64 cols][68]
    const float gm = gamma[0];

    #pragma unroll
    for(int chunk=0; chunk<4; chunk++){
        if(chunk==0)      asm volatile("cp.async.wait_group 3;" ::: "memory");
        else if(chunk==1) asm volatile("cp.async.wait_group 2;" ::: "memory");
        else if(chunk==2) asm volatile("cp.async.wait_group 1;" ::: "memory");
        else              asm volatile("cp.async.wait_group 0;" ::: "memory");
        __syncthreads();  // chunk staged; prev chunk's tr reads done

        const bf16* WoC = (const bf16*)(smr + wo_off[chunk]);
        float acc[4][4];
        #pragma unroll
        for(int bn=0;bn<4;bn++)
            #pragma unroll
            for(int q=0;q<4;q++) acc[bn][q]=0.f;

        #pragma unroll
        for(int ks=0; ks<16; ks++){
            u32 af[4];
            const bf16* ar = ctxs + (size_t)(wm*16 + g)*264 + ks*16 + 2*tig;
            af[0] = *(const u32*)ar;
            af[1] = *(const u32*)(ar + 8*264);
            af[2] = *(const u32*)(ar + 8);
            af[3] = *(const u32*)(ar + 8*264 + 8);
            #pragma unroll
            for(int bn=0;bn<4;bn++){
                const bf16* br = WoC + (size_t)(kh*32 + bn*8 + g)*264 + ks*16 + 2*tig;
                u32 b0 = *(const u32*)br, b1 = *(const u32*)(br + 8);
                mma16816(acc[bn], af, b0, b1);
            }
        }
        __syncthreads();  // (also guards tr from any stragglers)

        {
            int rl = wm*16 + g;
            #pragma unroll
            for(int bn=0;bn<4;bn++){
                int col = kh*32 + bn*8 + 2*tig;
                tr[col*68 + rl]         = acc[bn][0];
                tr[(col+1)*68 + rl]     = acc[bn][1];
                tr[col*68 + rl + 8]     = acc[bn][2];
                tr[(col+1)*68 + rl + 8] = acc[bn][3];
            }
        }
        __syncthreads();

        {
            int cc = t >> 2, q4 = t & 3;
            int c = chunk*64 + cc;
            float scl = bn_scale[c] * rsqrtf(bn_var[c] + EPSV);
            float mu  = bn_mean[c];
            float bi  = bn_bias[c];
            const float* xr = x   + ((size_t)(b*CC) + c)*HWN + n0 + q4*16;
            float* orow     = out + ((size_t)(b*CC) + c)*HWN + n0 + q4*16;
            #pragma unroll
            for(int q=0;q<4;q++){
                float4 xv = *(const float4*)(xr + q*4);
                float4 o;
                float v0 = tr[cc*68 + q4*16 + q*4 + 0];
                float v1 = tr[cc*68 + q4*16 + q*4 + 1];
                float v2 = tr[cc*68 + q4*16 + q*4 + 2];
                float v3 = tr[cc*68 + q4*16 + q*4 + 3];
                o.x = gm*fmaxf((v0-mu)*scl+bi, 0.f) + xv.x;
                o.y = gm*fmaxf((v1-mu)*scl+bi, 0.f) + xv.y;
                o.z = gm*fmaxf((v2-mu)*scl+bi, 0.f) + xv.z;
                o.w = gm*fmaxf((v3-mu)*scl+bi, 0.f) + xv.w;
                *(float4*)(orow + q*4) = o;
            }
        }
    }
}

// ---------------- launch ----------------
extern "C" void kernel_launch(void* const* d_in, const int* in_sizes, int n_in,
                              void* d_out, int out_size){
    (void)in_sizes; (void)n_in; (void)out_size;
    const float* x        = (const float*)d_in[0];
    const float* Wq       = (const float*)d_in[1];
    const float* Wk       = (const float*)d_in[2];
    const float* Wv       = (const float*)d_in[3];
    const float* Wb1      = (const float*)d_in[4];
    const float* Wb2      = (const float*)d_in[5];
    const float* w_gb     = (const float*)d_in[6];
    const float* ge_w1    = (const float*)d_in[7];
    const float* ge_b1    = (const float*)d_in[8];
    const float* ge_w2    = (const float*)d_in[9];
    const float* ge_b2    = (const float*)d_in[10];
    const float* Wo       = (const float*)d_in[11];
    const float* bn_scale = (const float*)d_in[12];
    const float* bn_bias  = (const float*)d_in[13];
    const float* bn_mean  = (const float*)d_in[14];
    const float* bn_var   = (const float*)d_in[15];
    const float* gamma    = (const float*)d_in[16];
    float* out = (float*)d_out;

    cudaFuncSetAttribute(k_attn,   cudaFuncAttributeMaxDynamicSharedMemorySize, ATTN_SMEM);
    cudaFuncSetAttribute(k_projmm, cudaFuncAttributeMaxDynamicSharedMemorySize, PJ_SMEM);

    k_mean  <<<dim3(CC/8, BB), 256>>>(x);
    k_gate  <<<BB, 256>>>(ge_w1, ge_b1, ge_w2, ge_b2);
    k_xpose <<<dim3(HWN/128, CC/32, BB), 128>>>(x);
    k_wprep <<<(BB*NO*CC + CC*CC)/256, 256>>>(Wq, Wk, Wb1, Wb2, Wv, Wo);
    k_projmm<<<dim3(HWN/128, NO/64, BB), 128, PJ_SMEM>>>();
    k_smooth<<<(BB*HWN*KCN)/256, 256>>>();
    k_attn  <<<dim3(HWN/64, BB), 256, ATTN_SMEM>>>(w_gb, x, bn_scale, bn_bias,
                                                   bn_mean, bn_var, gamma, out);
}